// round 1
// baseline (speedup 1.0000x reference)
#include <cuda_runtime.h>

// Problem shape (fixed for this bench)
#define D       512
#define NROWS   65536
#define MCODES  4096

// GEMM tiling
#define BM 128
#define BN 128
#define BK 16

// Scratch (device globals: no allocation allowed in kernel_launch)
__device__ unsigned long long g_best[NROWS];   // packed (sortable_score, ~idx)
__device__ float              g_halfcsq[MCODES];

__device__ __forceinline__ unsigned int f2sortable(float f) {
    unsigned int u = __float_as_uint(f);
    return (u & 0x80000000u) ? ~u : (u | 0x80000000u);
}

__global__ void k_init() {
    int i = blockIdx.x * blockDim.x + threadIdx.x;
    if (i < NROWS) g_best[i] = 0ull;   // 0 == lowest possible packed score
}

// halfcsq[m] = 0.5 * ||codebook[m]||^2   (one warp per codebook row)
__global__ void k_csq(const float* __restrict__ cb) {
    int warp = (blockIdx.x * blockDim.x + threadIdx.x) >> 5;
    int lane = threadIdx.x & 31;
    if (warp >= MCODES) return;
    const float* row = cb + (size_t)warp * D;
    float s = 0.f;
    #pragma unroll 4
    for (int t = lane; t < D; t += 32) { float v = row[t]; s += v * v; }
    #pragma unroll
    for (int o = 16; o > 0; o >>= 1) s += __shfl_xor_sync(0xffffffffu, s, o);
    if (lane == 0) g_halfcsq[warp] = 0.5f * s;
}

// Fused GEMM (scores = emb . cb^T) + per-row argmax epilogue.
// CTA tile: BM x BN, K-loop over full D. 256 threads, 8x8 per-thread microtile.
__global__ void __launch_bounds__(256, 2)
k_gemm_argmax(const float* __restrict__ A, const float* __restrict__ B) {
    __shared__ __align__(16) float As[2][BK][BM];
    __shared__ __align__(16) float Bs[2][BK][BN];

    const int tid   = threadIdx.x;
    const int mTile = blockIdx.x;           // 0..31  (M fastest -> L2 reuse of A tile)
    const int nTile = blockIdx.y;           // 0..511
    const int rowBase = nTile * BM;
    const int colBase = mTile * BN;

    // global-load mapping: each thread loads 2 float4 of A and 2 of B per K-tile
    const int ldRow = tid >> 2;             // 0..63
    const int ldK   = (tid & 3) << 2;       // 0,4,8,12

    const float* Abase = A + (size_t)(rowBase + ldRow) * D + ldK;
    const float* Bbase = B + (size_t)(colBase + ldRow) * D + ldK;

    // compute mapping
    const int ty = tid >> 4;                // 0..15 -> rows ty*4+{0..3}, +64
    const int tx = tid & 15;                // 0..15 -> cols tx*4+{0..3}, +64

    float acc[8][8];
    #pragma unroll
    for (int i = 0; i < 8; ++i)
        #pragma unroll
        for (int j = 0; j < 8; ++j) acc[i][j] = 0.f;

    float4 a0, a1, b0, b1;

    // prologue: load K-tile 0
    a0 = *(const float4*)(Abase);
    a1 = *(const float4*)(Abase + (size_t)64 * D);
    b0 = *(const float4*)(Bbase);
    b1 = *(const float4*)(Bbase + (size_t)64 * D);
    {
        As[0][ldK + 0][ldRow] = a0.x; As[0][ldK + 1][ldRow] = a0.y;
        As[0][ldK + 2][ldRow] = a0.z; As[0][ldK + 3][ldRow] = a0.w;
        As[0][ldK + 0][ldRow + 64] = a1.x; As[0][ldK + 1][ldRow + 64] = a1.y;
        As[0][ldK + 2][ldRow + 64] = a1.z; As[0][ldK + 3][ldRow + 64] = a1.w;
        Bs[0][ldK + 0][ldRow] = b0.x; Bs[0][ldK + 1][ldRow] = b0.y;
        Bs[0][ldK + 2][ldRow] = b0.z; Bs[0][ldK + 3][ldRow] = b0.w;
        Bs[0][ldK + 0][ldRow + 64] = b1.x; Bs[0][ldK + 1][ldRow + 64] = b1.y;
        Bs[0][ldK + 2][ldRow + 64] = b1.z; Bs[0][ldK + 3][ldRow + 64] = b1.w;
    }
    __syncthreads();

    const int nIter = D / BK;               // 32
    #pragma unroll 1
    for (int t = 0; t < nIter; ++t) {
        const int cur = t & 1;
        if (t + 1 < nIter) {
            const int kt = (t + 1) * BK;
            a0 = *(const float4*)(Abase + kt);
            a1 = *(const float4*)(Abase + (size_t)64 * D + kt);
            b0 = *(const float4*)(Bbase + kt);
            b1 = *(const float4*)(Bbase + (size_t)64 * D + kt);
        }
        #pragma unroll
        for (int k = 0; k < BK; ++k) {
            float4 av0 = *(const float4*)&As[cur][k][ty * 4];
            float4 av1 = *(const float4*)&As[cur][k][ty * 4 + 64];
            float4 bv0 = *(const float4*)&Bs[cur][k][tx * 4];
            float4 bv1 = *(const float4*)&Bs[cur][k][tx * 4 + 64];
            float a[8] = {av0.x, av0.y, av0.z, av0.w, av1.x, av1.y, av1.z, av1.w};
            float b[8] = {bv0.x, bv0.y, bv0.z, bv0.w, bv1.x, bv1.y, bv1.z, bv1.w};
            #pragma unroll
            for (int i = 0; i < 8; ++i)
                #pragma unroll
                for (int j = 0; j < 8; ++j)
                    acc[i][j] = fmaf(a[i], b[j], acc[i][j]);
        }
        if (t + 1 < nIter) {
            const int nxt = 1 - cur;
            As[nxt][ldK + 0][ldRow] = a0.x; As[nxt][ldK + 1][ldRow] = a0.y;
            As[nxt][ldK + 2][ldRow] = a0.z; As[nxt][ldK + 3][ldRow] = a0.w;
            As[nxt][ldK + 0][ldRow + 64] = a1.x; As[nxt][ldK + 1][ldRow + 64] = a1.y;
            As[nxt][ldK + 2][ldRow + 64] = a1.z; As[nxt][ldK + 3][ldRow + 64] = a1.w;
            Bs[nxt][ldK + 0][ldRow] = b0.x; Bs[nxt][ldK + 1][ldRow] = b0.y;
            Bs[nxt][ldK + 2][ldRow] = b0.z; Bs[nxt][ldK + 3][ldRow] = b0.w;
            Bs[nxt][ldK + 0][ldRow + 64] = b1.x; Bs[nxt][ldK + 1][ldRow + 64] = b1.y;
            Bs[nxt][ldK + 2][ldRow + 64] = b1.z; Bs[nxt][ldK + 3][ldRow + 64] = b1.w;
            __syncthreads();
        }
    }

    // ---- epilogue: per-row argmax of score = acc - 0.5*||c||^2 ----
    // pack (sortable_score << 32) | (0xFFFFFFFF - col): max => best score,
    // smaller index wins ties (matches jnp.argmin first-min semantics).
    unsigned long long myBest[8];
    #pragma unroll
    for (int i = 0; i < 8; ++i) {
        unsigned long long best = 0ull;
        #pragma unroll
        for (int j = 0; j < 8; ++j) {
            int col = colBase + tx * 4 + (j & 3) + (j >> 2) * 64;
            float s = acc[i][j] - __ldg(&g_halfcsq[col]);
            unsigned long long p =
                ((unsigned long long)f2sortable(s) << 32) |
                (unsigned long long)(0xFFFFFFFFu - (unsigned)col);
            best = (p > best) ? p : best;
        }
        myBest[i] = best;
    }
    // reduce across tx (16 lanes; xor offsets < 16 stay within the half-warp group)
    #pragma unroll
    for (int o = 1; o < 16; o <<= 1) {
        #pragma unroll
        for (int i = 0; i < 8; ++i) {
            unsigned long long other = __shfl_xor_sync(0xffffffffu, myBest[i], o);
            myBest[i] = (other > myBest[i]) ? other : myBest[i];
        }
    }
    if (tx == 0) {
        #pragma unroll
        for (int i = 0; i < 8; ++i) {
            int row = rowBase + ty * 4 + (i & 3) + (i >> 2) * 64;
            atomicMax(&g_best[row], myBest[i]);
        }
    }
}

// quantized[n] = codebook[idx[n]]; optional indices (as float) at out + N*D
__global__ void k_gather(const float* __restrict__ cb, float* __restrict__ out,
                         float* __restrict__ idx_out) {
    int n = blockIdx.x;
    unsigned long long p = g_best[n];
    unsigned idx = 0xFFFFFFFFu - (unsigned)(p & 0xFFFFFFFFull);
    const float4* src = (const float4*)(cb + (size_t)idx * D);
    float4* dst = (float4*)(out + (size_t)n * D);
    dst[threadIdx.x] = src[threadIdx.x];        // 128 threads x float4 = 512 floats
    if (threadIdx.x == 0 && idx_out) idx_out[n] = (float)idx;
}

extern "C" void kernel_launch(void* const* d_in, const int* in_sizes, int n_in,
                              void* d_out, int out_size) {
    const float* emb = (const float*)d_in[0];   // [65536, 512] f32
    const float* cb  = (const float*)d_in[1];   // [4096, 512]  f32
    float* out = (float*)d_out;

    // quantized first ([N,D]); indices (cast to f32) appended if out buffer has room
    float* idx_out = nullptr;
    long long need = (long long)NROWS * D + NROWS;
    if ((long long)out_size >= need) idx_out = out + (size_t)NROWS * D;

    k_init<<<NROWS / 1024, 1024>>>();
    k_csq<<<MCODES / 8, 256>>>(cb);

    dim3 grid(MCODES / BN, NROWS / BM);         // (32, 512), M fastest for L2 A-reuse
    k_gemm_argmax<<<grid, 256>>>(emb, cb);

    k_gather<<<NROWS, 128>>>(cb, out, idx_out);
}

// round 5
// speedup vs baseline: 2.0612x; 2.0612x over previous
#include <cuda_runtime.h>
#include <cuda_bf16.h>
#include <cstdint>

#define D        512
#define NROWS    65536
#define MCODES   4096
#define BM       256
#define BN       128
#define BK       32
#define NKC      (D / BK)        // 16
#define NTILES_R (NROWS / BM)    // 256
#define NTILES_C (MCODES / BN)   // 32
#define THRESH   0.004f

// ---------------- scratch (device globals; no allocations allowed) ----------
#define A_BLK (BM * BK * 2)      // 16384 B per (rt,kc) block per plane
#define B_BLK (BN * BK * 2)      // 8192 B
__device__ __align__(128) unsigned char sAh[(size_t)NTILES_R * NKC * A_BLK]; // 64MB
__device__ __align__(128) unsigned char sAl[(size_t)NTILES_R * NKC * A_BLK]; // 64MB
__device__ __align__(128) unsigned char sBh[(size_t)NTILES_C * NKC * B_BLK]; // 4MB
__device__ __align__(128) unsigned char sBl[(size_t)NTILES_C * NKC * B_BLK]; // 4MB

__device__ float              g_halfcsq[MCODES];
__device__ unsigned long long g_cand[NROWS][NTILES_C][2];
__device__ int                g_idx[NROWS];
__device__ int                g_flag_count;
__device__ int                g_flag_list[NROWS];

// ---------------- helpers ----------------------------------------------------
__device__ __forceinline__ unsigned int f2sortable(float f) {
    unsigned int u = __float_as_uint(f);
    return (u & 0x80000000u) ? ~u : (u | 0x80000000u);
}
__device__ __forceinline__ float sortable2f(unsigned int u) {
    unsigned int b = (u & 0x80000000u) ? (u ^ 0x80000000u) : ~u;
    return __uint_as_float(b);
}
__device__ __forceinline__ unsigned long long packSI(float s, int col) {
    return ((unsigned long long)f2sortable(s) << 32) |
           (unsigned long long)(0xFFFFFFFFu - (unsigned)col);
}
__device__ __forceinline__ void top2merge(unsigned long long& b1, unsigned long long& b2,
                                          unsigned long long o1, unsigned long long o2) {
    if (o1 > b1) { b2 = (b1 > o2) ? b1 : o2; b1 = o1; }
    else if (o1 > b2) { b2 = o1; }
}
__device__ __forceinline__ uint32_t smem_u32(const void* p) {
    uint32_t a;
    asm("{ .reg .u64 t; cvta.to.shared.u64 t, %1; cvt.u32.u64 %0, t; }" : "=r"(a) : "l"(p));
    return a;
}

// ---------------- cp.async / ldmatrix / mma ----------------------------------
__device__ __forceinline__ void cp16(uint32_t dst, const void* src) {
    asm volatile("cp.async.cg.shared.global [%0], [%1], 16;" :: "r"(dst), "l"(src) : "memory");
}
#define CP_COMMIT() asm volatile("cp.async.commit_group;" ::: "memory")
#define CP_WAIT(N)  asm volatile("cp.async.wait_group %0;" :: "n"(N) : "memory")

#define LDM4(r, addr) \
    asm volatile("ldmatrix.sync.aligned.m8n8.x4.shared.b16 {%0,%1,%2,%3}, [%4];" \
        : "=r"((r)[0]), "=r"((r)[1]), "=r"((r)[2]), "=r"((r)[3]) : "r"(addr))

#define MMA(d, a, b0_, b1_) \
    asm volatile("mma.sync.aligned.m16n8k16.row.col.f32.bf16.bf16.f32 " \
        "{%0,%1,%2,%3},{%4,%5,%6,%7},{%8,%9},{%0,%1,%2,%3};" \
        : "+f"((d)[0]), "+f"((d)[1]), "+f"((d)[2]), "+f"((d)[3]) \
        : "r"((a)[0]), "r"((a)[1]), "r"((a)[2]), "r"((a)[3]), "r"(b0_), "r"(b1_))

// ---------------- SMEM layout (GEMM) -----------------------------------------
#define ST_AH 0
#define ST_AL 16384
#define ST_BH 32768
#define ST_BL 40960
#define STG   49152
#define SMEM_TOTAL (2 * STG)     // 98304

// ---------------- pre-split: fp32 -> tile-blocked bf16 hi/lo -----------------
__device__ __forceinline__ uint32_t bf2u(__nv_bfloat162 v) {
    return *reinterpret_cast<uint32_t*>(&v);
}
__device__ __forceinline__ void cvt_store8(const float* __restrict__ src,
                                           unsigned char* dstH, unsigned char* dstL) {
    float4 v0 = *(const float4*)(src);
    float4 v1 = *(const float4*)(src + 4);
    __nv_bfloat162 h0 = __floats2bfloat162_rn(v0.x, v0.y);
    __nv_bfloat162 h1 = __floats2bfloat162_rn(v0.z, v0.w);
    __nv_bfloat162 h2 = __floats2bfloat162_rn(v1.x, v1.y);
    __nv_bfloat162 h3 = __floats2bfloat162_rn(v1.z, v1.w);
    __nv_bfloat162 l0 = __floats2bfloat162_rn(v0.x - __bfloat162float(h0.x),
                                              v0.y - __bfloat162float(h0.y));
    __nv_bfloat162 l1 = __floats2bfloat162_rn(v0.z - __bfloat162float(h1.x),
                                              v0.w - __bfloat162float(h1.y));
    __nv_bfloat162 l2 = __floats2bfloat162_rn(v1.x - __bfloat162float(h2.x),
                                              v1.y - __bfloat162float(h2.y));
    __nv_bfloat162 l3 = __floats2bfloat162_rn(v1.z - __bfloat162float(h3.x),
                                              v1.w - __bfloat162float(h3.y));
    *(uint4*)dstH = make_uint4(bf2u(h0), bf2u(h1), bf2u(h2), bf2u(h3));
    *(uint4*)dstL = make_uint4(bf2u(l0), bf2u(l1), bf2u(l2), bf2u(l3));
}

// A: block (rt,kc) = 4 chunks x 256 rows of uint4 at offset (c*256+r)*16
__global__ void k_split_a(const float* __restrict__ A) {
    int bx = blockIdx.x;                 // rt*NKC + kc
    int rt = bx >> 4, kc = bx & 15;
    unsigned char* dh = sAh + (size_t)bx * A_BLK;
    unsigned char* dl = sAl + (size_t)bx * A_BLK;
    #pragma unroll
    for (int i = 0; i < 4; ++i) {
        int g = threadIdx.x + i * 256;   // 0..1023
        int c = g >> 8, r = g & 255;
        cvt_store8(A + (size_t)(rt * BM + r) * D + kc * BK + c * 8,
                   dh + g * 16, dl + g * 16);
    }
}

// B: block (ct,kc) = 4 chunks x 128 cols of uint4 at offset (c*128+r)*16
__global__ void k_split_b(const float* __restrict__ B) {
    int bx = blockIdx.x;                 // ct*NKC + kc
    int ct = bx >> 4, kc = bx & 15;
    unsigned char* dh = sBh + (size_t)bx * B_BLK;
    unsigned char* dl = sBl + (size_t)bx * B_BLK;
    #pragma unroll
    for (int i = 0; i < 2; ++i) {
        int g = threadIdx.x + i * 256;   // 0..511
        int c = g >> 7, r = g & 127;
        cvt_store8(B + (size_t)(ct * BN + r) * D + kc * BK + c * 8,
                   dh + g * 16, dl + g * 16);
    }
}

// ---------------- misc kernels ----------------------------------------------
__global__ void k_init() { if (threadIdx.x == 0) g_flag_count = 0; }

__global__ void k_csq(const float* __restrict__ cb) {
    int warp = (blockIdx.x * blockDim.x + threadIdx.x) >> 5;
    int lane = threadIdx.x & 31;
    if (warp >= MCODES) return;
    const float* row = cb + (size_t)warp * D;
    float s = 0.f;
    #pragma unroll 4
    for (int t = lane; t < D; t += 32) { float v = row[t]; s += v * v; }
    #pragma unroll
    for (int o = 16; o > 0; o >>= 1) s += __shfl_xor_sync(0xffffffffu, s, o);
    if (lane == 0) g_halfcsq[warp] = 0.5f * s;
}

// ---------------- main GEMM (mma.sync bf16 split) + top2 epilogue -----------
__global__ void __launch_bounds__(256, 1)
k_gemm() {
    extern __shared__ char smem[];
    const uint32_t sb = smem_u32(smem);
    const int tid  = threadIdx.x;
    const int wid  = tid >> 5;
    const int lane = tid & 31;
    const int ct = blockIdx.x;           // 0..31  (fastest -> A tile L2 reuse)
    const int rt = blockIdx.y;           // 0..255
    const int wr = wid >> 1;             // 0..3 -> rows wr*64 .. +63
    const int wc = wid & 1;              // 0..1 -> cols wc*64 .. +63

    // ---- async stage loader: contiguous 16B copies from blocked planes ----
    const unsigned char* a_h = sAh + (size_t)(rt * NKC) * A_BLK;
    const unsigned char* a_l = sAl + (size_t)(rt * NKC) * A_BLK;
    const unsigned char* b_h = sBh + (size_t)(ct * NKC) * B_BLK;
    const unsigned char* b_l = sBl + (size_t)(ct * NKC) * B_BLK;

    auto load_stage = [&](int kc, int s) {
        const uint32_t st = sb + s * STG;
        const unsigned char* ah = a_h + (size_t)kc * A_BLK;
        const unsigned char* al = a_l + (size_t)kc * A_BLK;
        const unsigned char* bh = b_h + (size_t)kc * B_BLK;
        const unsigned char* bl = b_l + (size_t)kc * B_BLK;
        #pragma unroll
        for (int i = 0; i < 4; ++i) {
            int o = (tid + i * 256) * 16;
            cp16(st + ST_AH + o, ah + o);
            cp16(st + ST_AL + o, al + o);
        }
        #pragma unroll
        for (int i = 0; i < 2; ++i) {
            int o = (tid + i * 256) * 16;
            cp16(st + ST_BH + o, bh + o);
            cp16(st + ST_BL + o, bl + o);
        }
    };

    // ldmatrix per-lane address pieces
    const int rowA = wr * 64 + (lane & 7) + ((lane >> 3) & 1) * 8;  // + m*16
    const int chA  = (lane >> 4);                                    // + 2*step
    const int colB = wc * 64 + (lane & 7) + (lane >> 4) * 8;         // + np*16
    const int chB  = ((lane >> 3) & 1);                              // + 2*step

    float acc[4][8][4];
    #pragma unroll
    for (int m = 0; m < 4; ++m)
        #pragma unroll
        for (int n = 0; n < 8; ++n)
            #pragma unroll
            for (int q = 0; q < 4; ++q) acc[m][n][q] = 0.f;

    load_stage(0, 0);
    CP_COMMIT();

    #pragma unroll 1
    for (int kc = 0; kc < NKC; ++kc) {
        const int s = kc & 1;
        if (kc + 1 < NKC) { load_stage(kc + 1, 1 - s); CP_COMMIT(); CP_WAIT(1); }
        else              { CP_WAIT(0); }
        __syncthreads();

        const uint32_t st = sb + s * STG;
        #pragma unroll
        for (int step = 0; step < 2; ++step) {
            uint32_t aH[4][4], aL[4][4];
            #pragma unroll
            for (int m = 0; m < 4; ++m) {
                uint32_t off = (uint32_t)(((chA + 2 * step) * 256 + rowA + m * 16) * 16);
                LDM4(aH[m], st + ST_AH + off);
                LDM4(aL[m], st + ST_AL + off);
            }
            #pragma unroll
            for (int np = 0; np < 4; ++np) {
                uint32_t bH[4], bL[4];
                uint32_t off = (uint32_t)(((chB + 2 * step) * 128 + colB + np * 16) * 16);
                LDM4(bH, st + ST_BH + off);
                LDM4(bL, st + ST_BL + off);
                // product-major order -> same-acc mmas are 8 apart
                #pragma unroll
                for (int m = 0; m < 4; ++m) {
                    MMA(acc[m][2 * np],     aH[m], bH[0], bH[1]);
                    MMA(acc[m][2 * np + 1], aH[m], bH[2], bH[3]);
                }
                #pragma unroll
                for (int m = 0; m < 4; ++m) {
                    MMA(acc[m][2 * np],     aL[m], bH[0], bH[1]);
                    MMA(acc[m][2 * np + 1], aL[m], bH[2], bH[3]);
                }
                #pragma unroll
                for (int m = 0; m < 4; ++m) {
                    MMA(acc[m][2 * np],     aH[m], bL[0], bL[1]);
                    MMA(acc[m][2 * np + 1], aH[m], bL[2], bL[3]);
                }
            }
        }
        __syncthreads();
    }

    // ---- epilogue: top2 per row over this CTA's 128 cols ----
    const int colBase = ct * BN + wc * 64 + (lane & 3) * 2;
    float hc[8][2];
    #pragma unroll
    for (int n = 0; n < 8; ++n) {
        hc[n][0] = __ldg(&g_halfcsq[colBase + n * 8]);
        hc[n][1] = __ldg(&g_halfcsq[colBase + n * 8 + 1]);
    }

    unsigned long long* ep = (unsigned long long*)smem;  // [2][256][2] = 8KB (stage0 done)
    #pragma unroll
    for (int m = 0; m < 4; ++m) {
        #pragma unroll
        for (int rv = 0; rv < 2; ++rv) {
            unsigned long long b1 = 0ull, b2 = 0ull;
            #pragma unroll
            for (int n = 0; n < 8; ++n) {
                int col = colBase + n * 8;
                unsigned long long p0 = packSI(acc[m][n][2 * rv]     - hc[n][0], col);
                unsigned long long p1 = packSI(acc[m][n][2 * rv + 1] - hc[n][1], col + 1);
                top2merge(b1, b2, p0, 0ull);
                top2merge(b1, b2, p1, 0ull);
            }
            #pragma unroll
            for (int o = 1; o < 4; o <<= 1) {
                unsigned long long o1 = __shfl_xor_sync(0xffffffffu, b1, o);
                unsigned long long o2 = __shfl_xor_sync(0xffffffffu, b2, o);
                top2merge(b1, b2, o1, o2);
            }
            if ((lane & 3) == 0) {
                int rowL = wr * 64 + m * 16 + (lane >> 2) + rv * 8;
                ep[(wc * 256 + rowL) * 2 + 0] = b1;
                ep[(wc * 256 + rowL) * 2 + 1] = b2;
            }
        }
    }
    __syncthreads();
    {
        int rowL = tid;                   // 256 rows, 256 threads
        unsigned long long b1 = ep[(0 * 256 + rowL) * 2 + 0];
        unsigned long long b2 = ep[(0 * 256 + rowL) * 2 + 1];
        top2merge(b1, b2, ep[(1 * 256 + rowL) * 2 + 0], ep[(1 * 256 + rowL) * 2 + 1]);
        g_cand[rt * BM + rowL][ct][0] = b1;
        g_cand[rt * BM + rowL][ct][1] = b2;
    }
}

// ---------------- reduce + exact rescue + gather -----------------------------
__global__ void k_reduce() {
    int row = blockIdx.x * blockDim.x + threadIdx.x;
    if (row >= NROWS) return;
    const unsigned long long* c = &g_cand[row][0][0];
    unsigned long long b1 = 0ull, b2 = 0ull;
    #pragma unroll 8
    for (int e = 0; e < NTILES_C * 2; ++e) {
        unsigned long long v = c[e];
        if (v > b1) { b2 = b1; b1 = v; }
        else if (v > b2) { b2 = v; }
    }
    g_idx[row] = (int)(0xFFFFFFFFu - (unsigned)(b1 & 0xFFFFFFFFull));
    float s1 = sortable2f((unsigned)(b1 >> 32));
    float s2 = sortable2f((unsigned)(b2 >> 32));
    if (s1 - s2 < THRESH) {
        int slot = atomicAdd(&g_flag_count, 1);
        if (slot < NROWS) g_flag_list[slot] = row;
    }
}

__global__ void __launch_bounds__(256)
k_exact(const float* __restrict__ A, const float* __restrict__ B) {
    __shared__ float xrow[D];
    __shared__ unsigned long long wbest[8];
    const int tid = threadIdx.x, wid = tid >> 5, lid = tid & 31;
    const int count = g_flag_count;
    for (int i = blockIdx.x; i < count; i += gridDim.x) {
        const int row = g_flag_list[i];
        __syncthreads();
        for (int j = tid; j < D; j += 256) xrow[j] = A[(size_t)row * D + j];
        __syncthreads();
        unsigned long long best = 0ull;
        for (int m = wid; m < MCODES; m += 8) {
            const float* cp = B + (size_t)m * D;
            float s = 0.f;
            #pragma unroll
            for (int t = 0; t < 4; ++t) {
                float4 cv = *(const float4*)(cp + t * 128 + lid * 4);
                float4 xv = *(const float4*)(xrow + t * 128 + lid * 4);
                s += cv.x * xv.x + cv.y * xv.y + cv.z * xv.z + cv.w * xv.w;
            }
            #pragma unroll
            for (int o = 16; o > 0; o >>= 1) s += __shfl_xor_sync(0xffffffffu, s, o);
            unsigned long long p = packSI(s - g_halfcsq[m], m);
            if (p > best) best = p;
        }
        if (lid == 0) wbest[wid] = best;
        __syncthreads();
        if (tid == 0) {
            unsigned long long bb = wbest[0];
            #pragma unroll
            for (int w = 1; w < 8; ++w) if (wbest[w] > bb) bb = wbest[w];
            g_idx[row] = (int)(0xFFFFFFFFu - (unsigned)(bb & 0xFFFFFFFFull));
        }
    }
}

__global__ void k_gather(const float* __restrict__ cb, float* __restrict__ out,
                         float* __restrict__ idx_out) {
    int n = blockIdx.x;
    int idx = g_idx[n];
    const float4* src = (const float4*)(cb + (size_t)idx * D);
    float4* dst = (float4*)(out + (size_t)n * D);
    dst[threadIdx.x] = src[threadIdx.x];
    if (threadIdx.x == 0 && idx_out) idx_out[n] = (float)idx;
}

// ---------------- launch ----------------------------------------------------
extern "C" void kernel_launch(void* const* d_in, const int* in_sizes, int n_in,
                              void* d_out, int out_size) {
    const float* emb = (const float*)d_in[0];   // [65536, 512] f32
    const float* cb  = (const float*)d_in[1];   // [4096, 512]  f32
    float* out = (float*)d_out;

    float* idx_out = nullptr;
    long long need = (long long)NROWS * D + NROWS;
    if ((long long)out_size >= need) idx_out = out + (size_t)NROWS * D;

    cudaFuncSetAttribute(k_gemm, cudaFuncAttributeMaxDynamicSharedMemorySize, SMEM_TOTAL);

    k_init<<<1, 32>>>();
    k_csq<<<MCODES / 8, 256>>>(cb);
    k_split_a<<<NTILES_R * NKC, 256>>>(emb);    // 4096 blocks
    k_split_b<<<NTILES_C * NKC, 256>>>(cb);     // 512 blocks

    dim3 grid(NTILES_C, NTILES_R);              // (32, 256)
    k_gemm<<<grid, 256, SMEM_TOTAL>>>();

    k_reduce<<<NROWS / 256, 256>>>();
    k_exact<<<128, 256>>>(emb, cb);
    k_gather<<<NROWS, 128>>>(cb, out, idx_out);
}

// round 7
// speedup vs baseline: 3.7006x; 1.7954x over previous
#include <cuda_runtime.h>
#include <cstdint>

#define D        512
#define NROWS    65536
#define MCODES   4096
#define BM       128
#define BN       128
#define BK       32
#define NKC      (D / BK)        // 16
#define NT_R     (NROWS / BM)    // 512
#define NT_C     (MCODES / BN)   // 32
#define NGRP     (NT_C * 4)      // 128 col-groups of 32 per row
#define THRESH   0.05f

// ---------------- scratch (device globals) -----------------------------------
#define A_BLK 4096               // 128 rows x 32 int8 per (rt,kc) block
#define B_BLK 4096
__device__ __align__(128) unsigned char qAh[(size_t)NT_R * NKC * A_BLK]; // 32MB
__device__ __align__(128) unsigned char qAl[(size_t)NT_R * NKC * A_BLK]; // 32MB
__device__ __align__(128) unsigned char qBh[(size_t)NT_C * NKC * B_BLK]; // 2MB
__device__ __align__(128) unsigned char qBl[(size_t)NT_C * NKC * B_BLK]; // 2MB

__device__ float              g_sA[NROWS];
__device__ float              g_sB[MCODES];
__device__ float              g_halfcsq[MCODES];
__device__ unsigned long long g_cand[(size_t)NROWS * NGRP * 2];  // 128MB
__device__ int                g_idx[NROWS];
__device__ int                g_flag_count;
__device__ int                g_flag_list[NROWS];

// ---------------- helpers ----------------------------------------------------
__device__ __forceinline__ unsigned int f2sortable(float f) {
    unsigned int u = __float_as_uint(f);
    return (u & 0x80000000u) ? ~u : (u | 0x80000000u);
}
__device__ __forceinline__ float sortable2f(unsigned int u) {
    unsigned int b = (u & 0x80000000u) ? (u ^ 0x80000000u) : ~u;
    return __uint_as_float(b);
}
__device__ __forceinline__ unsigned long long packSI(float s, int col) {
    return ((unsigned long long)f2sortable(s) << 32) |
           (unsigned long long)(0xFFFFFFFFu - (unsigned)col);
}
__device__ __forceinline__ void top2merge(unsigned long long& b1, unsigned long long& b2,
                                          unsigned long long o1, unsigned long long o2) {
    if (o1 > b1) { b2 = (b1 > o2) ? b1 : o2; b1 = o1; }
    else if (o1 > b2) { b2 = o1; }
}
__device__ __forceinline__ uint32_t smem_u32(const void* p) {
    uint32_t a;
    asm("{ .reg .u64 t; cvta.to.shared.u64 t, %1; cvt.u32.u64 %0, t; }" : "=r"(a) : "l"(p));
    return a;
}

// ---------------- cp.async / ldmatrix / mma ----------------------------------
__device__ __forceinline__ void cp16(uint32_t dst, const void* src) {
    asm volatile("cp.async.cg.shared.global [%0], [%1], 16;" :: "r"(dst), "l"(src) : "memory");
}
#define CP_COMMIT() asm volatile("cp.async.commit_group;" ::: "memory")
#define CP_WAIT(N)  asm volatile("cp.async.wait_group %0;" :: "n"(N) : "memory")

#define LDM4(r, addr) \
    asm volatile("ldmatrix.sync.aligned.m8n8.x4.shared.b16 {%0,%1,%2,%3}, [%4];" \
        : "=r"((r)[0]), "=r"((r)[1]), "=r"((r)[2]), "=r"((r)[3]) : "r"(addr))

#define MMAI8(d, a, b0_, b1_) \
    asm volatile("mma.sync.aligned.m16n8k32.row.col.s32.s8.s8.s32 " \
        "{%0,%1,%2,%3},{%4,%5,%6,%7},{%8,%9},{%0,%1,%2,%3};" \
        : "+r"((d)[0]), "+r"((d)[1]), "+r"((d)[2]), "+r"((d)[3]) \
        : "r"((a)[0]), "r"((a)[1]), "r"((a)[2]), "r"((a)[3]), "r"(b0_), "r"(b1_))

// ---------------- stage layout -----------------------------------------------
#define ST_AH 0
#define ST_AL 4096
#define ST_BH 8192
#define ST_BL 12288
#define STG   16384
#define NSTAGE 4
#define SMEM_TOTAL (NSTAGE * STG)   // 65536

// ---------------- quantization -----------------------------------------------
__device__ __forceinline__ uint32_t pack4(int q0, int q1, int q2, int q3) {
    return (uint32_t)(q0 & 0xFF) | ((uint32_t)(q1 & 0xFF) << 8) |
           ((uint32_t)(q2 & 0xFF) << 16) | ((uint32_t)(q3 & 0xFF) << 24);
}

__device__ __forceinline__ void quant_row(const float* __restrict__ X, int row,
                                          unsigned char* __restrict__ ph,
                                          unsigned char* __restrict__ pl,
                                          float* __restrict__ scale_out,
                                          float* __restrict__ halfcsq_out) {
    const int lane = threadIdx.x & 31;
    const float4* xp = (const float4*)(X + (size_t)row * D + lane * 16);
    float4 v[4];
    float amax = 0.f, ssq = 0.f;
    #pragma unroll
    for (int i = 0; i < 4; ++i) {
        v[i] = xp[i];
        amax = fmaxf(amax, fmaxf(fmaxf(fabsf(v[i].x), fabsf(v[i].y)),
                                 fmaxf(fabsf(v[i].z), fabsf(v[i].w))));
        if (halfcsq_out)
            ssq += v[i].x * v[i].x + v[i].y * v[i].y + v[i].z * v[i].z + v[i].w * v[i].w;
    }
    #pragma unroll
    for (int o = 16; o > 0; o >>= 1) {
        amax = fmaxf(amax, __shfl_xor_sync(0xffffffffu, amax, o));
        if (halfcsq_out) ssq += __shfl_xor_sync(0xffffffffu, ssq, o);
    }
    amax = fmaxf(amax, 1e-30f);
    const float inv = 127.f / amax;
    uint32_t H[4], L[4];
    #pragma unroll
    for (int i = 0; i < 4; ++i) {
        float f[4] = {v[i].x, v[i].y, v[i].z, v[i].w};
        int qh[4], ql[4];
        #pragma unroll
        for (int j = 0; j < 4; ++j) {
            float t = f[j] * inv;
            qh[j] = __float2int_rn(t);
            qh[j] = max(-127, min(127, qh[j]));
            float rh = t - (float)qh[j];
            ql[j] = __float2int_rn(rh * 128.f);
        }
        H[i] = pack4(qh[0], qh[1], qh[2], qh[3]);
        L[i] = pack4(ql[0], ql[1], ql[2], ql[3]);
    }
    const int rt  = row >> 7;
    const int rIn = row & 127;
    const int kc  = lane >> 1;
    const int c   = lane & 1;
    const size_t off = (size_t)(rt * NKC + kc) * 4096 + (size_t)(c * 128 + rIn) * 16;
    *(uint4*)(ph + off) = make_uint4(H[0], H[1], H[2], H[3]);
    *(uint4*)(pl + off) = make_uint4(L[0], L[1], L[2], L[3]);
    if (lane == 0) {
        scale_out[row] = amax / 127.f;
        if (halfcsq_out) halfcsq_out[row] = 0.5f * ssq;
    }
}

__global__ void k_quant_a(const float* __restrict__ A) {
    int row = blockIdx.x * 8 + (threadIdx.x >> 5);
    if (row < NROWS) quant_row(A, row, qAh, qAl, g_sA, nullptr);
}
__global__ void k_quant_b(const float* __restrict__ B) {
    int row = blockIdx.x * 8 + (threadIdx.x >> 5);
    if (row < MCODES) quant_row(B, row, qBh, qBl, g_sB, g_halfcsq);
}

__global__ void k_init() { if (threadIdx.x == 0) g_flag_count = 0; }

// ---------------- main GEMM: int8 double-digit, 3 products -------------------
__global__ void __launch_bounds__(256)
k_gemm() {
    extern __shared__ char smem[];
    const uint32_t sb = smem_u32(smem);
    const int tid  = threadIdx.x;
    const int wid  = tid >> 5;
    const int lane = tid & 31;
    const int ct = blockIdx.x;           // 0..31  fastest -> B L2-resident, A-tile reuse
    const int rt = blockIdx.y;           // 0..511
    const int wr = wid >> 2;             // 0..1 -> rows wr*64..+63
    const int wc = wid & 3;              // 0..3 -> cols wc*32..+31

    const unsigned char* aH = qAh + (size_t)(rt * NKC) * A_BLK;
    const unsigned char* aL = qAl + (size_t)(rt * NKC) * A_BLK;
    const unsigned char* bH = qBh + (size_t)(ct * NKC) * B_BLK;
    const unsigned char* bL = qBl + (size_t)(ct * NKC) * B_BLK;

    auto load_stage = [&](int kc) {
        const uint32_t st = sb + (kc & (NSTAGE - 1)) * STG;
        const uint32_t o = tid * 16;
        cp16(st + ST_AH + o, aH + (size_t)kc * A_BLK + o);
        cp16(st + ST_AL + o, aL + (size_t)kc * A_BLK + o);
        cp16(st + ST_BH + o, bH + (size_t)kc * B_BLK + o);
        cp16(st + ST_BL + o, bL + (size_t)kc * B_BLK + o);
    };

    // ldmatrix lane address pieces (A: mats = {rows0-7,k0-15},{rows8-15,k0-15},
    //                                        {rows0-7,k16-31},{rows8-15,k16-31})
    const int mtx = lane >> 3;
    const int aC = mtx >> 1;
    const int aR = (mtx & 1) * 8 + (lane & 7);
    const int bC = mtx & 1;
    const int bR = (mtx >> 1) * 8 + (lane & 7);
    const uint32_t aOffBase = (uint32_t)((aC * 128 + wr * 64 + aR) * 16);
    const uint32_t bOffBase = (uint32_t)((bC * 128 + wc * 32 + bR) * 16);

    int acc1[4][4][4], acc2[4][4][4];
    #pragma unroll
    for (int m = 0; m < 4; ++m)
        #pragma unroll
        for (int n = 0; n < 4; ++n)
            #pragma unroll
            for (int q = 0; q < 4; ++q) { acc1[m][n][q] = 0; acc2[m][n][q] = 0; }

    load_stage(0); CP_COMMIT();
    load_stage(1); CP_COMMIT();
    load_stage(2); CP_COMMIT();

    #pragma unroll 1
    for (int kc = 0; kc < NKC; ++kc) {
        if (kc < NKC - 2)       { CP_WAIT(2); }
        else if (kc == NKC - 2) { CP_WAIT(1); }
        else                    { CP_WAIT(0); }
        __syncthreads();
        if (kc + 3 < NKC) { load_stage(kc + 3); CP_COMMIT(); }

        const uint32_t st = sb + (kc & (NSTAGE - 1)) * STG;
        uint32_t ah[4][4], al[4][4], bh[2][4], bl[2][4];
        #pragma unroll
        for (int m = 0; m < 4; ++m) {
            uint32_t ad = st + aOffBase + (uint32_t)(m * 16 * 16);
            LDM4(ah[m], ad + ST_AH);
            LDM4(al[m], ad + ST_AL);
        }
        #pragma unroll
        for (int np = 0; np < 2; ++np) {
            uint32_t bd = st + bOffBase + (uint32_t)(np * 16 * 16);
            LDM4(bh[np], bd + ST_BH);
            LDM4(bl[np], bd + ST_BL);
        }
        // P1: qh*ch -> acc1 (exact int32)
        #pragma unroll
        for (int m = 0; m < 4; ++m)
            #pragma unroll
            for (int np = 0; np < 2; ++np) {
                MMAI8(acc1[m][2 * np],     ah[m], bh[np][0], bh[np][1]);
                MMAI8(acc1[m][2 * np + 1], ah[m], bh[np][2], bh[np][3]);
            }
        // P2: qh*cl -> acc2
        #pragma unroll
        for (int m = 0; m < 4; ++m)
            #pragma unroll
            for (int np = 0; np < 2; ++np) {
                MMAI8(acc2[m][2 * np],     ah[m], bl[np][0], bl[np][1]);
                MMAI8(acc2[m][2 * np + 1], ah[m], bl[np][2], bl[np][3]);
            }
        // P3: ql*ch -> acc2 (shares accumulator, exact int32 sum)
        #pragma unroll
        for (int m = 0; m < 4; ++m)
            #pragma unroll
            for (int np = 0; np < 2; ++np) {
                MMAI8(acc2[m][2 * np],     al[m], bh[np][0], bh[np][1]);
                MMAI8(acc2[m][2 * np + 1], al[m], bh[np][2], bh[np][3]);
            }
    }

    // ---- epilogue: per (row, 32-col group) top2 ----
    const int g   = lane >> 2;
    const int tig = lane & 3;
    float sb2[4][2], hc[4][2];
    int colg[4];
    #pragma unroll
    for (int j = 0; j < 4; ++j) {
        colg[j] = ct * BN + wc * 32 + j * 8 + tig * 2;
        sb2[j][0] = __ldg(&g_sB[colg[j]]);      sb2[j][1] = __ldg(&g_sB[colg[j] + 1]);
        hc[j][0]  = __ldg(&g_halfcsq[colg[j]]); hc[j][1]  = __ldg(&g_halfcsq[colg[j] + 1]);
    }
    #pragma unroll
    for (int m = 0; m < 4; ++m) {
        #pragma unroll
        for (int rv = 0; rv < 2; ++rv) {
            const int row = rt * BM + wr * 64 + m * 16 + g + rv * 8;
            const float sa = __ldg(&g_sA[row]);
            unsigned long long b1 = 0ull, b2 = 0ull;
            #pragma unroll
            for (int j = 0; j < 4; ++j) {
                #pragma unroll
                for (int q = 0; q < 2; ++q) {
                    float v = (float)acc1[m][j][2 * rv + q] +
                              (float)acc2[m][j][2 * rv + q] * (1.0f / 128.0f);
                    float s = sa * sb2[j][q] * v - hc[j][q];
                    top2merge(b1, b2, packSI(s, colg[j] + q), 0ull);
                }
            }
            #pragma unroll
            for (int o = 1; o < 4; o <<= 1) {
                unsigned long long o1 = __shfl_xor_sync(0xffffffffu, b1, o);
                unsigned long long o2 = __shfl_xor_sync(0xffffffffu, b2, o);
                top2merge(b1, b2, o1, o2);
            }
            if (tig == 0) {
                size_t base = ((size_t)row * NGRP + (ct * 4 + wc)) * 2;
                g_cand[base]     = b1;
                g_cand[base + 1] = b2;
            }
        }
    }
}

// ---------------- reduce (warp per row) --------------------------------------
__global__ void k_reduce() {
    const int lane = threadIdx.x & 31;
    const int row  = blockIdx.x * 8 + (threadIdx.x >> 5);
    if (row >= NROWS) return;
    const unsigned long long* c = g_cand + (size_t)row * NGRP * 2;
    unsigned long long b1 = 0ull, b2 = 0ull;
    #pragma unroll
    for (int k = 0; k < 8; ++k) {
        unsigned long long v = c[lane + 32 * k];
        top2merge(b1, b2, v, 0ull);
    }
    #pragma unroll
    for (int o = 16; o > 0; o >>= 1) {
        unsigned long long o1 = __shfl_xor_sync(0xffffffffu, b1, o);
        unsigned long long o2 = __shfl_xor_sync(0xffffffffu, b2, o);
        top2merge(b1, b2, o1, o2);
    }
    if (lane == 0) {
        g_idx[row] = (int)(0xFFFFFFFFu - (unsigned)(b1 & 0xFFFFFFFFull));
        float s1 = sortable2f((unsigned)(b1 >> 32));
        float s2 = sortable2f((unsigned)(b2 >> 32));
        if (s1 - s2 < THRESH) {
            int slot = atomicAdd(&g_flag_count, 1);
            if (slot < NROWS) g_flag_list[slot] = row;
        }
    }
}

// ---------------- rescue: exact fp32 re-rank of candidate set ----------------
#define CLIST_MAX 128
__global__ void __launch_bounds__(256)
k_rescue(const float* __restrict__ A, const float* __restrict__ B) {
    __shared__ float xrow[D];
    __shared__ unsigned long long sbest;
    __shared__ int clist[CLIST_MAX];
    __shared__ int ccount;
    const int tid = threadIdx.x, wid = tid >> 5, lid = tid & 31;
    const int count = min(g_flag_count, NROWS);
    for (int i = blockIdx.x; i < count; i += gridDim.x) {
        const int row = g_flag_list[i];
        __syncthreads();
        if (tid == 0) { sbest = 0ull; ccount = 0; }
        for (int j = tid; j < D; j += 256) xrow[j] = A[(size_t)row * D + j];
        __syncthreads();
        const unsigned long long* c = g_cand + (size_t)row * NGRP * 2;
        unsigned long long amax = 0ull;
        for (int e = tid; e < NGRP * 2; e += 256) {
            unsigned long long v = c[e];
            if (v > amax) amax = v;
        }
        atomicMax(&sbest, amax);
        __syncthreads();
        const unsigned thrU = f2sortable(sortable2f((unsigned)(sbest >> 32)) - THRESH);
        for (int e = tid; e < NGRP * 2; e += 256) {
            unsigned long long v = c[e];
            if ((unsigned)(v >> 32) >= thrU) {
                int slot = atomicAdd(&ccount, 1);
                if (slot < CLIST_MAX)
                    clist[slot] = (int)(0xFFFFFFFFu - (unsigned)(v & 0xFFFFFFFFull));
            }
        }
        __syncthreads();
        if (tid == 0) sbest = 0ull;
        __syncthreads();
        const int nc = min(ccount, CLIST_MAX);
        for (int k = wid; k < nc; k += 8) {
            const int m = clist[k];
            const float* cp = B + (size_t)m * D;
            float s = 0.f;
            #pragma unroll
            for (int t = 0; t < 4; ++t) {
                float4 cv = *(const float4*)(cp + t * 128 + lid * 4);
                float4 xv = *(const float4*)(xrow + t * 128 + lid * 4);
                s += cv.x * xv.x + cv.y * xv.y + cv.z * xv.z + cv.w * xv.w;
            }
            #pragma unroll
            for (int o = 16; o > 0; o >>= 1) s += __shfl_xor_sync(0xffffffffu, s, o);
            if (lid == 0) atomicMax(&sbest, packSI(s - __ldg(&g_halfcsq[m]), m));
        }
        __syncthreads();
        if (tid == 0)
            g_idx[row] = (int)(0xFFFFFFFFu - (unsigned)(sbest & 0xFFFFFFFFull));
    }
}

__global__ void k_gather(const float* __restrict__ cb, float* __restrict__ out,
                         float* __restrict__ idx_out) {
    int n = blockIdx.x;
    int idx = g_idx[n];
    const float4* src = (const float4*)(cb + (size_t)idx * D);
    float4* dst = (float4*)(out + (size_t)n * D);
    dst[threadIdx.x] = src[threadIdx.x];
    if (threadIdx.x == 0 && idx_out) idx_out[n] = (float)idx;
}

// ---------------- launch ----------------------------------------------------
extern "C" void kernel_launch(void* const* d_in, const int* in_sizes, int n_in,
                              void* d_out, int out_size) {
    const float* emb = (const float*)d_in[0];   // [65536, 512] f32
    const float* cb  = (const float*)d_in[1];   // [4096, 512]  f32
    float* out = (float*)d_out;

    float* idx_out = nullptr;
    long long need = (long long)NROWS * D + NROWS;
    if ((long long)out_size >= need) idx_out = out + (size_t)NROWS * D;

    cudaFuncSetAttribute(k_gemm, cudaFuncAttributeMaxDynamicSharedMemorySize, SMEM_TOTAL);

    k_init<<<1, 32>>>();
    k_quant_a<<<NROWS / 8, 256>>>(emb);
    k_quant_b<<<MCODES / 8, 256>>>(cb);

    dim3 grid(NT_C, NT_R);                      // (32, 512), ct fastest
    k_gemm<<<grid, 256, SMEM_TOTAL>>>();

    k_reduce<<<NROWS / 8, 256>>>();
    k_rescue<<<512, 256>>>(emb, cb);
    k_gather<<<NROWS, 128>>>(cb, out, idx_out);
}

// round 8
// speedup vs baseline: 3.7550x; 1.0147x over previous
#include <cuda_runtime.h>
#include <cstdint>

#define D        512
#define NROWS    65536
#define MCODES   4096
#define BM       128
#define BN       64
#define BK       32
#define NKC      (D / BK)        // 16
#define NT_R     (NROWS / BM)    // 512
#define NT_C     (MCODES / BN)   // 64
#define NGRP     NT_C            // one 64-col group per ct
#define THRESH   0.05f

// ---------------- scratch (device globals) -----------------------------------
#define A_BLK 4096               // 128 rows x 32 int8 per (rt,kc)
#define B_BLK 2048               // 64 rows x 32 int8 per (ct,kc)
__device__ __align__(128) unsigned char qAh[(size_t)NT_R * NKC * A_BLK]; // 32MB
__device__ __align__(128) unsigned char qAl[(size_t)NT_R * NKC * A_BLK]; // 32MB
__device__ __align__(128) unsigned char qBh[(size_t)NT_C * NKC * B_BLK]; // 2MB
__device__ __align__(128) unsigned char qBl[(size_t)NT_C * NKC * B_BLK]; // 2MB

__device__ float              g_sA[NROWS];
__device__ float              g_sB[MCODES];
__device__ float              g_halfcsq[MCODES];
__device__ unsigned long long g_cand[(size_t)NROWS * NGRP * 2];  // 67MB
__device__ int                g_idx[NROWS];
__device__ int                g_flag_count;
__device__ int                g_flag_list[NROWS];

// ---------------- helpers ----------------------------------------------------
__device__ __forceinline__ unsigned int f2sortable(float f) {
    unsigned int u = __float_as_uint(f);
    return (u & 0x80000000u) ? ~u : (u | 0x80000000u);
}
__device__ __forceinline__ float sortable2f(unsigned int u) {
    unsigned int b = (u & 0x80000000u) ? (u ^ 0x80000000u) : ~u;
    return __uint_as_float(b);
}
__device__ __forceinline__ unsigned long long packSI(float s, int col) {
    return ((unsigned long long)f2sortable(s) << 32) |
           (unsigned long long)(0xFFFFFFFFu - (unsigned)col);
}
__device__ __forceinline__ void top2merge(unsigned long long& b1, unsigned long long& b2,
                                          unsigned long long o1, unsigned long long o2) {
    if (o1 > b1) { b2 = (b1 > o2) ? b1 : o2; b1 = o1; }
    else if (o1 > b2) { b2 = o1; }
}
__device__ __forceinline__ uint32_t smem_u32(const void* p) {
    uint32_t a;
    asm("{ .reg .u64 t; cvta.to.shared.u64 t, %1; cvt.u32.u64 %0, t; }" : "=r"(a) : "l"(p));
    return a;
}

// ---------------- cp.async / ldmatrix / mma ----------------------------------
__device__ __forceinline__ void cp16(uint32_t dst, const void* src) {
    asm volatile("cp.async.cg.shared.global [%0], [%1], 16;" :: "r"(dst), "l"(src) : "memory");
}
#define CP_COMMIT() asm volatile("cp.async.commit_group;" ::: "memory")
#define CP_WAIT(N)  asm volatile("cp.async.wait_group %0;" :: "n"(N) : "memory")

#define LDM4(r, addr) \
    asm volatile("ldmatrix.sync.aligned.m8n8.x4.shared.b16 {%0,%1,%2,%3}, [%4];" \
        : "=r"((r)[0]), "=r"((r)[1]), "=r"((r)[2]), "=r"((r)[3]) : "r"(addr))

#define MMAI8(d, a, b0_, b1_) \
    asm volatile("mma.sync.aligned.m16n8k32.row.col.s32.s8.s8.s32 " \
        "{%0,%1,%2,%3},{%4,%5,%6,%7},{%8,%9},{%0,%1,%2,%3};" \
        : "+r"((d)[0]), "+r"((d)[1]), "+r"((d)[2]), "+r"((d)[3]) \
        : "r"((a)[0]), "r"((a)[1]), "r"((a)[2]), "r"((a)[3]), "r"(b0_), "r"(b1_))

// ---------------- stage layout -----------------------------------------------
#define ST_AH 0
#define ST_AL 4096
#define ST_BH 8192
#define ST_BL 10240
#define STG   12288
#define NSTAGE 4
#define SMEM_TOTAL (NSTAGE * STG)   // 49152

// ---------------- quantization -----------------------------------------------
__device__ __forceinline__ uint32_t pack4(int q0, int q1, int q2, int q3) {
    return (uint32_t)(q0 & 0xFF) | ((uint32_t)(q1 & 0xFF) << 8) |
           ((uint32_t)(q2 & 0xFF) << 16) | ((uint32_t)(q3 & 0xFF) << 24);
}

template<int RSHIFT, int BLKSZ>
__device__ __forceinline__ void quant_row(const float* __restrict__ X, int row,
                                          unsigned char* __restrict__ ph,
                                          unsigned char* __restrict__ pl,
                                          float* __restrict__ scale_out,
                                          float* __restrict__ halfcsq_out) {
    const int lane = threadIdx.x & 31;
    const float4* xp = (const float4*)(X + (size_t)row * D + lane * 16);
    float4 v[4];
    float amax = 0.f, ssq = 0.f;
    #pragma unroll
    for (int i = 0; i < 4; ++i) {
        v[i] = xp[i];
        amax = fmaxf(amax, fmaxf(fmaxf(fabsf(v[i].x), fabsf(v[i].y)),
                                 fmaxf(fabsf(v[i].z), fabsf(v[i].w))));
        if (halfcsq_out)
            ssq += v[i].x * v[i].x + v[i].y * v[i].y + v[i].z * v[i].z + v[i].w * v[i].w;
    }
    #pragma unroll
    for (int o = 16; o > 0; o >>= 1) {
        amax = fmaxf(amax, __shfl_xor_sync(0xffffffffu, amax, o));
        if (halfcsq_out) ssq += __shfl_xor_sync(0xffffffffu, ssq, o);
    }
    amax = fmaxf(amax, 1e-30f);
    const float inv = 127.f / amax;
    uint32_t H[4], L[4];
    #pragma unroll
    for (int i = 0; i < 4; ++i) {
        float f[4] = {v[i].x, v[i].y, v[i].z, v[i].w};
        int qh[4], ql[4];
        #pragma unroll
        for (int j = 0; j < 4; ++j) {
            float t = f[j] * inv;
            qh[j] = __float2int_rn(t);
            qh[j] = max(-127, min(127, qh[j]));
            float rh = t - (float)qh[j];
            ql[j] = __float2int_rn(rh * 128.f);
        }
        H[i] = pack4(qh[0], qh[1], qh[2], qh[3]);
        L[i] = pack4(ql[0], ql[1], ql[2], ql[3]);
    }
    const int rt  = row >> RSHIFT;
    const int rIn = row & ((1 << RSHIFT) - 1);
    const int kc  = lane >> 1;
    const int c   = lane & 1;
    const size_t off = (size_t)(rt * NKC + kc) * BLKSZ +
                       (size_t)(c * (1 << RSHIFT) + rIn) * 16;
    *(uint4*)(ph + off) = make_uint4(H[0], H[1], H[2], H[3]);
    *(uint4*)(pl + off) = make_uint4(L[0], L[1], L[2], L[3]);
    if (lane == 0) {
        scale_out[row] = amax / 127.f;
        if (halfcsq_out) halfcsq_out[row] = 0.5f * ssq;
    }
}

__global__ void k_quant_a(const float* __restrict__ A) {
    int row = blockIdx.x * 8 + (threadIdx.x >> 5);
    if (row < NROWS) quant_row<7, A_BLK>(A, row, qAh, qAl, g_sA, nullptr);
}
__global__ void k_quant_b(const float* __restrict__ B) {
    int row = blockIdx.x * 8 + (threadIdx.x >> 5);
    if (row < MCODES) quant_row<6, B_BLK>(B, row, qBh, qBl, g_sB, g_halfcsq);
}

__global__ void k_init() { if (threadIdx.x == 0) g_flag_count = 0; }

// ---------------- main GEMM: int8 double-digit, 3 products -------------------
// 256 thr, 2 CTAs/SM. Warp grid 2x4: warp tile 64 rows x 16 cols.
__global__ void __launch_bounds__(256, 2)
k_gemm() {
    extern __shared__ char smem[];
    const uint32_t sb = smem_u32(smem);
    const int tid  = threadIdx.x;
    const int wid  = tid >> 5;
    const int lane = tid & 31;
    const int ct = blockIdx.x;           // 0..63 fastest -> B fully L2-resident
    const int rt = blockIdx.y;           // 0..511
    const int wr = wid >> 2;             // 0..1 -> rows wr*64..+63
    const int wc = wid & 3;              // 0..3 -> cols wc*16..+15

    const unsigned char* aH = qAh + (size_t)(rt * NKC) * A_BLK;
    const unsigned char* aL = qAl + (size_t)(rt * NKC) * A_BLK;
    const unsigned char* bH = qBh + (size_t)(ct * NKC) * B_BLK;
    const unsigned char* bL = qBl + (size_t)(ct * NKC) * B_BLK;

    auto load_stage = [&](int kc) {
        const uint32_t st = sb + (kc & (NSTAGE - 1)) * STG;
        const uint32_t o = tid * 16;
        cp16(st + ST_AH + o, aH + (size_t)kc * A_BLK + o);
        cp16(st + ST_AL + o, aL + (size_t)kc * A_BLK + o);
        if (tid < 128) cp16(st + ST_BH + o, bH + (size_t)kc * B_BLK + o);
        else           cp16(st + ST_BL + (o - 2048), bL + (size_t)kc * B_BLK + (o - 2048));
    };

    // ldmatrix lane address pieces
    const int mtx = lane >> 3;
    const uint32_t aOff = (uint32_t)((mtx >> 1) * 2048 +
                          (wr * 64 + (mtx & 1) * 8 + (lane & 7)) * 16);
    const uint32_t bOff = (uint32_t)((mtx & 1) * 1024 +
                          (wc * 16 + (mtx >> 1) * 8 + (lane & 7)) * 16);

    int acc1[4][2][4], acc2[4][2][4];
    #pragma unroll
    for (int m = 0; m < 4; ++m)
        #pragma unroll
        for (int n = 0; n < 2; ++n)
            #pragma unroll
            for (int q = 0; q < 4; ++q) { acc1[m][n][q] = 0; acc2[m][n][q] = 0; }

    load_stage(0); CP_COMMIT();
    load_stage(1); CP_COMMIT();
    load_stage(2); CP_COMMIT();

    #pragma unroll 1
    for (int kc = 0; kc < NKC; ++kc) {
        if (kc < NKC - 2)       { CP_WAIT(2); }
        else if (kc == NKC - 2) { CP_WAIT(1); }
        else                    { CP_WAIT(0); }
        __syncthreads();
        if (kc + 3 < NKC) { load_stage(kc + 3); CP_COMMIT(); }

        const uint32_t st = sb + (kc & (NSTAGE - 1)) * STG;
        uint32_t bh[4], bl[4];
        LDM4(bh, st + ST_BH + bOff);
        LDM4(bl, st + ST_BL + bOff);
        #pragma unroll
        for (int m = 0; m < 4; ++m) {
            uint32_t ah[4], al[4];
            const uint32_t ad = st + aOff + (uint32_t)(m * 256);
            LDM4(ah, ad + ST_AH);
            LDM4(al, ad + ST_AL);
            MMAI8(acc1[m][0], ah, bh[0], bh[1]);
            MMAI8(acc1[m][1], ah, bh[2], bh[3]);
            MMAI8(acc2[m][0], ah, bl[0], bl[1]);
            MMAI8(acc2[m][1], ah, bl[2], bl[3]);
            MMAI8(acc2[m][0], al, bh[0], bh[1]);
            MMAI8(acc2[m][1], al, bh[2], bh[3]);
        }
    }

    // ---- epilogue: per-row top2 over this CTA's 64 cols ----
    const int tig = lane & 3;
    const int colBase = ct * BN + wc * 16 + tig * 2;
    float sb2[2][2], hc[2][2];
    #pragma unroll
    for (int f = 0; f < 2; ++f) {
        sb2[f][0] = __ldg(&g_sB[colBase + f * 8]);
        sb2[f][1] = __ldg(&g_sB[colBase + f * 8 + 1]);
        hc[f][0]  = __ldg(&g_halfcsq[colBase + f * 8]);
        hc[f][1]  = __ldg(&g_halfcsq[colBase + f * 8 + 1]);
    }
    unsigned long long* ep = (unsigned long long*)smem;  // [4][128][2] = 8KB
    #pragma unroll
    for (int m = 0; m < 4; ++m) {
        #pragma unroll
        for (int rv = 0; rv < 2; ++rv) {
            const int rowL = wr * 64 + m * 16 + (lane >> 2) + rv * 8;
            const float sa = __ldg(&g_sA[rt * BM + rowL]);
            unsigned long long b1 = 0ull, b2 = 0ull;
            #pragma unroll
            for (int f = 0; f < 2; ++f)
                #pragma unroll
                for (int q = 0; q < 2; ++q) {
                    float v = (float)acc1[m][f][2 * rv + q] +
                              (float)acc2[m][f][2 * rv + q] * (1.0f / 128.0f);
                    float s = sa * sb2[f][q] * v - hc[f][q];
                    top2merge(b1, b2, packSI(s, colBase + f * 8 + q), 0ull);
                }
            #pragma unroll
            for (int o = 1; o < 4; o <<= 1) {
                unsigned long long o1 = __shfl_xor_sync(0xffffffffu, b1, o);
                unsigned long long o2 = __shfl_xor_sync(0xffffffffu, b2, o);
                top2merge(b1, b2, o1, o2);
            }
            if (tig == 0) {
                ep[(wc * 128 + rowL) * 2 + 0] = b1;
                ep[(wc * 128 + rowL) * 2 + 1] = b2;
            }
        }
    }
    __syncthreads();
    if (tid < 128) {
        const int rowL = tid;
        unsigned long long b1 = ep[rowL * 2 + 0];
        unsigned long long b2 = ep[rowL * 2 + 1];
        #pragma unroll
        for (int w = 1; w < 4; ++w)
            top2merge(b1, b2, ep[(w * 128 + rowL) * 2 + 0], ep[(w * 128 + rowL) * 2 + 1]);
        const size_t base = ((size_t)(rt * BM + rowL) * NGRP + ct) * 2;
        g_cand[base]     = b1;
        g_cand[base + 1] = b2;
    }
}

// ---------------- reduce (warp per row) --------------------------------------
__global__ void k_reduce() {
    const int lane = threadIdx.x & 31;
    const int row  = blockIdx.x * 8 + (threadIdx.x >> 5);
    if (row >= NROWS) return;
    const unsigned long long* c = g_cand + (size_t)row * NGRP * 2;
    unsigned long long b1 = 0ull, b2 = 0ull;
    #pragma unroll
    for (int k = 0; k < 4; ++k) {
        unsigned long long v = c[lane + 32 * k];
        top2merge(b1, b2, v, 0ull);
    }
    #pragma unroll
    for (int o = 16; o > 0; o >>= 1) {
        unsigned long long o1 = __shfl_xor_sync(0xffffffffu, b1, o);
        unsigned long long o2 = __shfl_xor_sync(0xffffffffu, b2, o);
        top2merge(b1, b2, o1, o2);
    }
    if (lane == 0) {
        g_idx[row] = (int)(0xFFFFFFFFu - (unsigned)(b1 & 0xFFFFFFFFull));
        float s1 = sortable2f((unsigned)(b1 >> 32));
        float s2 = sortable2f((unsigned)(b2 >> 32));
        if (s1 - s2 < THRESH) {
            int slot = atomicAdd(&g_flag_count, 1);
            if (slot < NROWS) g_flag_list[slot] = row;
        }
    }
}

// ---------------- rescue: exact fp32 re-rank of candidate set ----------------
#define CLIST_MAX 128
__global__ void __launch_bounds__(256)
k_rescue(const float* __restrict__ A, const float* __restrict__ B) {
    __shared__ float xrow[D];
    __shared__ unsigned long long sbest;
    __shared__ int clist[CLIST_MAX];
    __shared__ int ccount;
    const int tid = threadIdx.x, wid = tid >> 5, lid = tid & 31;
    const int count = min(g_flag_count, NROWS);
    for (int i = blockIdx.x; i < count; i += gridDim.x) {
        const int row = g_flag_list[i];
        __syncthreads();
        if (tid == 0) { sbest = 0ull; ccount = 0; }
        for (int j = tid; j < D; j += 256) xrow[j] = A[(size_t)row * D + j];
        __syncthreads();
        const unsigned long long* c = g_cand + (size_t)row * NGRP * 2;
        unsigned long long amax = 0ull;
        for (int e = tid; e < NGRP * 2; e += 256) {
            unsigned long long v = c[e];
            if (v > amax) amax = v;
        }
        atomicMax(&sbest, amax);
        __syncthreads();
        const unsigned thrU = f2sortable(sortable2f((unsigned)(sbest >> 32)) - THRESH);
        for (int e = tid; e < NGRP * 2; e += 256) {
            unsigned long long v = c[e];
            if ((unsigned)(v >> 32) >= thrU) {
                int slot = atomicAdd(&ccount, 1);
                if (slot < CLIST_MAX)
                    clist[slot] = (int)(0xFFFFFFFFu - (unsigned)(v & 0xFFFFFFFFull));
            }
        }
        __syncthreads();
        if (tid == 0) sbest = 0ull;
        __syncthreads();
        const int nc = min(ccount, CLIST_MAX);
        for (int k = wid; k < nc; k += 8) {
            const int m = clist[k];
            const float* cp = B + (size_t)m * D;
            float s = 0.f;
            #pragma unroll
            for (int t = 0; t < 4; ++t) {
                float4 cv = *(const float4*)(cp + t * 128 + lid * 4);
                float4 xv = *(const float4*)(xrow + t * 128 + lid * 4);
                s += cv.x * xv.x + cv.y * xv.y + cv.z * xv.z + cv.w * xv.w;
            }
            #pragma unroll
            for (int o = 16; o > 0; o >>= 1) s += __shfl_xor_sync(0xffffffffu, s, o);
            if (lid == 0) atomicMax(&sbest, packSI(s - __ldg(&g_halfcsq[m]), m));
        }
        __syncthreads();
        if (tid == 0)
            g_idx[row] = (int)(0xFFFFFFFFu - (unsigned)(sbest & 0xFFFFFFFFull));
    }
}

__global__ void k_gather(const float* __restrict__ cb, float* __restrict__ out,
                         float* __restrict__ idx_out) {
    int n = blockIdx.x;
    int idx = g_idx[n];
    const float4* src = (const float4*)(cb + (size_t)idx * D);
    float4* dst = (float4*)(out + (size_t)n * D);
    dst[threadIdx.x] = src[threadIdx.x];
    if (threadIdx.x == 0 && idx_out) idx_out[n] = (float)idx;
}

// ---------------- launch ----------------------------------------------------
extern "C" void kernel_launch(void* const* d_in, const int* in_sizes, int n_in,
                              void* d_out, int out_size) {
    const float* emb = (const float*)d_in[0];   // [65536, 512] f32
    const float* cb  = (const float*)d_in[1];   // [4096, 512]  f32
    float* out = (float*)d_out;

    float* idx_out = nullptr;
    long long need = (long long)NROWS * D + NROWS;
    if ((long long)out_size >= need) idx_out = out + (size_t)NROWS * D;

    cudaFuncSetAttribute(k_gemm, cudaFuncAttributeMaxDynamicSharedMemorySize, SMEM_TOTAL);

    k_init<<<1, 32>>>();
    k_quant_a<<<NROWS / 8, 256>>>(emb);
    k_quant_b<<<MCODES / 8, 256>>>(cb);

    dim3 grid(NT_C, NT_R);                      // (64, 512), ct fastest
    k_gemm<<<grid, 256, SMEM_TOTAL>>>();

    k_reduce<<<NROWS / 8, 256>>>();
    k_rescue<<<512, 256>>>(emb, cb);
    k_gather<<<NROWS, 128>>>(cb, out, idx_out);
}